// round 1
// baseline (speedup 1.0000x reference)
#include <cuda_runtime.h>
#include <math.h>

#define EPSF 1e-5f
#define PAD 3
#define TW 32
#define TH 8
#define TPW 38
#define TPH 14
#define TPIX (TPW*TPH)   /* 532 */

/* shared memory layout (float offsets) */
#define SM_X     0        /* 64*532 = 34048 floats; aliased by per-thread y (256*132) later */
#define SM_WR    34048    /* [c][r] 64*16, BN_r-folded w_reduce (transposed)  */
#define SM_BR    35072    /* 16    folded BN_r bias                            */
#define SM_WS    35088    /* [r][196] 16*196, w_span transposed                */
#define SM_BSPAN 38224    /* 196                                               */
#define SM_SI    38420    /* 64 BN_i scale                                     */
#define SM_SHI   38484    /* 64 BN_i shift                                     */
#define SM_W2    38548    /* [o][128]: [0:64)=scale_c*w_conv, [64:128)=scale_m*w_map */
#define SM_CST   54932    /* 128 combined output bias                          */
#define SM_FLOATS 55060
#define SMEM_BYTES (SM_FLOATS*4)

#define YSTRIDE 132       /* per-thread y vector stride (floats), 16B aligned, conflict-free LDS.128 */

__device__ __forceinline__ unsigned long long pk2(float a, float b) {
    unsigned long long r;
    asm("mov.b64 %0, {%1, %2};" : "=l"(r) : "r"(__float_as_uint(a)), "r"(__float_as_uint(b)));
    return r;
}
__device__ __forceinline__ unsigned long long ffma2(unsigned long long a, unsigned long long b,
                                                    unsigned long long c) {
    unsigned long long d;
    asm("fma.rn.f32x2 %0, %1, %2, %3;" : "=l"(d) : "l"(a), "l"(b), "l"(c));
    return d;
}
__device__ __forceinline__ void upk2(unsigned long long v, float& lo, float& hi) {
    unsigned int l, h;
    asm("mov.b64 {%0, %1}, %2;" : "=r"(l), "=r"(h) : "l"(v));
    lo = __uint_as_float(l); hi = __uint_as_float(h);
}
__device__ __forceinline__ float gelu_f(float v) {
    return 0.5f * v * (1.0f + erff(v * 0.70710678118654752f));
}

__global__ void __launch_bounds__(256, 1)
bneck_kernel(const float* __restrict__ x,
             const float* __restrict__ w_reduce,
             const float* __restrict__ g_r, const float* __restrict__ b_r,
             const float* __restrict__ m_r, const float* __restrict__ v_r,
             const float* __restrict__ w_span, const float* __restrict__ b_span,
             const float* __restrict__ g_i, const float* __restrict__ b_i,
             const float* __restrict__ m_i, const float* __restrict__ v_i,
             const float* __restrict__ w_conv,
             const float* __restrict__ g_c, const float* __restrict__ b_c,
             const float* __restrict__ m_c, const float* __restrict__ v_c,
             const float* __restrict__ w_map, const float* __restrict__ b_map,
             const float* __restrict__ g_m, const float* __restrict__ b_m,
             const float* __restrict__ m_m, const float* __restrict__ v_m,
             float* __restrict__ out)
{
    extern __shared__ float sm[];
    const int tid = threadIdx.x;
    const int bb  = blockIdx.z;
    const int h0  = blockIdx.y * TH;
    const int w0  = blockIdx.x * TW;

    /* ---------- load padded x tile into smem ---------- */
    {
        const int xbase = bb * 64 * 9216;
        for (int i = tid; i < 64 * TPIX; i += 256) {
            int c  = i / TPIX;
            int p  = i - c * TPIX;
            int r  = p / TPW;
            int cl = p - r * TPW;
            int gh = h0 + r - PAD;
            int gw = w0 + cl - PAD;
            float v = 0.f;
            if ((unsigned)gh < 96u && (unsigned)gw < 96u)
                v = x[xbase + c * 9216 + gh * 96 + gw];
            sm[SM_X + i] = v;
        }
    }

    /* ---------- fold BN into weights ---------- */
    for (int i = tid; i < 16 * 64; i += 256) {      /* wr_t[c][r] = scale_r[r]*w_reduce[r][c] */
        int c = i >> 4, r = i & 15;
        float sc = g_r[r] * rsqrtf(v_r[r] + EPSF);
        sm[SM_WR + c * 16 + r] = w_reduce[r * 64 + c] * sc;
    }
    if (tid < 16) {
        float sc = g_r[tid] * rsqrtf(v_r[tid] + EPSF);
        sm[SM_BR + tid] = b_r[tid] - m_r[tid] * sc;
    }
    for (int i = tid; i < 196 * 16; i += 256) {     /* ws_t[r][o] = w_span[o][r] */
        int o = i % 196, r = i / 196;
        sm[SM_WS + r * 196 + o] = w_span[o * 16 + r];
    }
    if (tid < 196) sm[SM_BSPAN + tid] = b_span[tid];
    if (tid < 64) {
        float sc = g_i[tid] * rsqrtf(v_i[tid] + EPSF);
        sm[SM_SI + tid]  = sc;
        sm[SM_SHI + tid] = b_i[tid] - m_i[tid] * sc;
    }
    for (int i = tid; i < 128 * 128; i += 256) {    /* W2[o][c2] */
        int o = i >> 7, c = i & 127;
        float v;
        if (c < 64) v = w_conv[o * 64 + c]        * (g_c[o] * rsqrtf(v_c[o] + EPSF));
        else        v = w_map [o * 64 + (c - 64)] * (g_m[o] * rsqrtf(v_m[o] + EPSF));
        sm[SM_W2 + i] = v;
    }
    if (tid < 128) {
        float sc_c = g_c[tid] * rsqrtf(v_c[tid] + EPSF);
        float sc_m = g_m[tid] * rsqrtf(v_m[tid] + EPSF);
        sm[SM_CST + tid] = (b_c[tid] - m_c[tid] * sc_c)
                         + sc_m * b_map[tid]
                         + (b_m[tid] - m_m[tid] * sc_m);
    }
    __syncthreads();

    /* ---------- per-pixel compute ---------- */
    const int px = tid & 31;
    const int py = tid >> 5;
    const float* xcen = sm + SM_X + (py + PAD) * TPW + (px + PAD);

    /* t = relu(folded reduce) */
    float t[16];
#pragma unroll
    for (int r = 0; r < 16; r++) t[r] = sm[SM_BR + r];
#pragma unroll
    for (int c = 0; c < 64; c++) {
        float xv = xcen[c * TPIX];
        const float4* w4 = (const float4*)(sm + SM_WR + c * 16);
#pragma unroll
        for (int q = 0; q < 4; q++) {
            float4 w = w4[q];
            t[4 * q + 0] = fmaf(w.x, xv, t[4 * q + 0]);
            t[4 * q + 1] = fmaf(w.y, xv, t[4 * q + 1]);
            t[4 * q + 2] = fmaf(w.z, xv, t[4 * q + 2]);
            t[4 * q + 3] = fmaf(w.w, xv, t[4 * q + 3]);
        }
    }
#pragma unroll
    for (int r = 0; r < 16; r++) t[r] = fmaxf(t[r], 0.f);

    /* per-group dynamic kernels + involution + BN_i + gelu */
    float x1[64];
#pragma unroll
    for (int g = 0; g < 4; g++) {
        float kg[49];
#pragma unroll
        for (int kk = 0; kk < 49; kk++) kg[kk] = sm[SM_BSPAN + g * 49 + kk];
#pragma unroll
        for (int r = 0; r < 16; r++) {
            float tv = t[r];
            const float* wsr = sm + SM_WS + r * 196 + g * 49;
#pragma unroll
            for (int kk = 0; kk < 49; kk++) kg[kk] = fmaf(wsr[kk], tv, kg[kk]);
        }
#pragma unroll
        for (int ci = 0; ci < 16; ci++) {
            int c = g * 16 + ci;
            const float* xb = sm + SM_X + c * TPIX + py * TPW + px;
            float acc = 0.f;
#pragma unroll
            for (int i = 0; i < 7; i++)
#pragma unroll
                for (int j = 0; j < 7; j++)
                    acc = fmaf(kg[i * 7 + j], xb[i * TPW + j], acc);
            float v = fmaf(acc, sm[SM_SI + c], sm[SM_SHI + c]);
            x1[c] = gelu_f(v);
        }
    }

    /* grab centers before we overwrite the x tile */
    float xc[64];
#pragma unroll
    for (int c = 0; c < 64; c++) xc[c] = xcen[c * TPIX];

    __syncthreads();   /* all reads of sm_x done in every thread */

    /* per-thread y = [gelu'd x1 (64) | x center (64)], aliases sm_x */
    float4* yq = (float4*)(sm + (size_t)tid * YSTRIDE);
#pragma unroll
    for (int q = 0; q < 16; q++)
        yq[q] = make_float4(x1[4 * q], x1[4 * q + 1], x1[4 * q + 2], x1[4 * q + 3]);
#pragma unroll
    for (int q = 0; q < 16; q++)
        yq[16 + q] = make_float4(xc[4 * q], xc[4 * q + 1], xc[4 * q + 2], xc[4 * q + 3]);

    /* fused 128x128 GEMV (conv+map, BN folded) with packed f32x2 FMAs */
    const int obase = bb * 128 * 9216 + (h0 + py) * 96 + (w0 + px);
#pragma unroll 1
    for (int ob = 0; ob < 8; ob++) {
        unsigned long long acc[16];
#pragma unroll
        for (int oo = 0; oo < 16; oo++) acc[oo] = 0ULL;
        const unsigned long long* w64 =
            (const unsigned long long*)(sm + SM_W2 + ob * 16 * 128);
#pragma unroll 1
        for (int cq = 0; cq < 32; cq++) {
            float4 y4 = yq[cq];
            unsigned long long ylo = pk2(y4.x, y4.y);
            unsigned long long yhi = pk2(y4.z, y4.w);
#pragma unroll
            for (int oo = 0; oo < 16; oo++) {
                acc[oo] = ffma2(w64[oo * 64 + 2 * cq],     ylo, acc[oo]);
                acc[oo] = ffma2(w64[oo * 64 + 2 * cq + 1], yhi, acc[oo]);
            }
        }
#pragma unroll
        for (int oo = 0; oo < 16; oo++) {
            float lo, hi;
            upk2(acc[oo], lo, hi);
            float s = lo + hi + sm[SM_CST + ob * 16 + oo];
            out[obase + (ob * 16 + oo) * 9216] = gelu_f(s);
        }
    }
}

extern "C" void kernel_launch(void* const* d_in, const int* in_sizes, int n_in,
                              void* d_out, int out_size)
{
    (void)in_sizes; (void)n_in; (void)out_size;
    const float* x        = (const float*)d_in[0];
    const float* w_reduce = (const float*)d_in[1];
    const float* g_r = (const float*)d_in[2];
    const float* b_r = (const float*)d_in[3];
    const float* m_r = (const float*)d_in[4];
    const float* v_r = (const float*)d_in[5];
    const float* w_span = (const float*)d_in[6];
    const float* b_span = (const float*)d_in[7];
    const float* g_i = (const float*)d_in[8];
    const float* b_i = (const float*)d_in[9];
    const float* m_i = (const float*)d_in[10];
    const float* v_i = (const float*)d_in[11];
    const float* w_conv = (const float*)d_in[12];
    const float* g_c = (const float*)d_in[13];
    const float* b_c = (const float*)d_in[14];
    const float* m_c = (const float*)d_in[15];
    const float* v_c = (const float*)d_in[16];
    const float* w_map = (const float*)d_in[17];
    const float* b_map = (const float*)d_in[18];
    const float* g_m = (const float*)d_in[19];
    const float* b_m = (const float*)d_in[20];
    const float* m_m = (const float*)d_in[21];
    const float* v_m = (const float*)d_in[22];
    float* out = (float*)d_out;

    cudaFuncSetAttribute(bneck_kernel, cudaFuncAttributeMaxDynamicSharedMemorySize, SMEM_BYTES);

    dim3 grid(96 / TW, 96 / TH, 4);   /* 3 x 12 x 4 = 144 blocks */
    dim3 block(256);
    bneck_kernel<<<grid, block, SMEM_BYTES>>>(
        x, w_reduce, g_r, b_r, m_r, v_r, w_span, b_span,
        g_i, b_i, m_i, v_i, w_conv, g_c, b_c, m_c, v_c,
        w_map, b_map, g_m, b_m, m_m, v_m, out);
}